// round 6
// baseline (speedup 1.0000x reference)
#include <cuda_runtime.h>

#define MAXN 20000
#define DIN  128
#define DHID 256
#define DDNS 128
#define NBLK 304          // residency proven at 304 blocks (152 SMs x 2 CTAs)
#define NTHR 512          // 1024 thr/SM -> 32 warps/SM for latency hiding

// Persistent scratch. RED accumulators are zero at module load; each run
// re-zeroes what it dirties AFTER last consumption -> replays see clean state.
__device__ float g_de[MAXN];            // RED: degree (no self-loop)
__device__ float g_se[MAXN];            // RED: edge part of s
__device__ float g_te[MAXN];            // RED: edge part of t
__device__ float g_ypart[NBLK][DIN];    // plain stores
__device__ float g_spart[NBLK];         // plain stores
__device__ float g_sum_s;               // plain store (phase 5)
__device__ float g_u[DHID];             // RED, zeroed phase 7
__device__ float g_g[DHID];             // RED, zeroed phase 8
__device__ float g_z[DDNS];             // RED, zeroed phase 8 (by consumer)
__device__ unsigned g_count;            // barrier count (self-resetting)
__device__ unsigned g_gen;              // barrier generation (monotonic ok)

__device__ __forceinline__ void grid_sync() {
    __syncthreads();
    if (threadIdx.x == 0) {
        __threadfence();
        unsigned gen = g_gen;
        if (atomicAdd(&g_count, 1u) == NBLK - 1u) {
            g_count = 0u;
            __threadfence();
            atomicExch(&g_gen, gen + 1u);
        } else {
            while (atomicAdd(&g_gen, 0u) == gen) __nanosleep(64);
            __threadfence();
        }
    }
    __syncthreads();
}

// ---------------------------------------------------------------------------
__global__ void __launch_bounds__(NTHR, 2)
k_main(const float* __restrict__ X,
       const int* __restrict__ row, const int* __restrict__ col,
       const float* __restrict__ w, int e, int n, int chunk,
       const float* __restrict__ W1,  const float* __restrict__ b1,
       const float* __restrict__ W2,  const float* __restrict__ b2,
       const float* __restrict__ Wd1, const float* __restrict__ bd1,
       const float* __restrict__ Wd2, const float* __restrict__ bd2,
       float* __restrict__ out, float invn) {
    const int tid    = threadIdx.x;
    const int t0     = blockIdx.x * NTHR + tid;
    const int stride = NBLK * NTHR;

    __shared__ float st[128];
    __shared__ float sacc[4][DIN];
    __shared__ float sred[16];
    __shared__ float svec[8];
    __shared__ float sp0[4], sp1[4];

    // ---- Phase 1: de[c] += w ----
    for (int i = t0; i < e; i += stride)
        atomicAdd(&g_de[col[i]], w[i]);
    grid_sync();

    // ---- Phase 2: se[r] += w * rsqrt(1 + de[c]) ----
    for (int i = t0; i < e; i += stride) {
        float de = __ldg(&g_de[col[i]]);
        atomicAdd(&g_se[row[i]], w[i] * rsqrtf(1.0f + de));
    }
    grid_sync();

    // ---- Phase 3: te[r] += w * di*(di*se + di^2) ----
    for (int i = t0; i < e; i += stride) {
        int c = col[i];
        float de = __ldg(&g_de[c]);
        float se = __ldg(&g_se[c]);
        float di = rsqrtf(1.0f + de);
        float s  = di * se + di * di;
        atomicAdd(&g_te[row[i]], w[i] * di * s);
    }
    grid_sync();

    // ---- Phase 4: y_part = X^T t over this block's row chunk; sum_s part ----
    // t = di*te + di^2*s ; s = di*se + di^2. Column-parallel: d = tid&127,
    // quarter = tid>>7 splits the row loop 4 ways. Re-zeroes de/se/te.
    {
        const int d       = tid & 127;
        const int quarter = tid >> 7;
        const int start   = blockIdx.x * chunk;
        const int end     = min(n, start + chunk);

        float acc  = 0.0f;
        float ssum = 0.0f;
        for (int base = start; base < end; base += 128) {
            int m = min(128, end - base);
            __syncthreads();
            if (tid < m) {
                int r = base + tid;
                float de = g_de[r];
                float se = g_se[r];
                float te = g_te[r];
                float di = rsqrtf(1.0f + de);
                float s  = di * se + di * di;
                st[tid] = di * te + di * di * s;
                ssum += s;
                g_de[r] = 0.0f; g_se[r] = 0.0f; g_te[r] = 0.0f;
            }
            __syncthreads();
            #pragma unroll 4
            for (int k = quarter; k < m; k += 4)
                acc += st[k] * __ldg(X + (size_t)(base + k) * DIN + d);
        }
        sacc[quarter][d] = acc;
        __syncthreads();
        if (tid < DIN)
            g_ypart[blockIdx.x][tid] = sacc[0][tid] + sacc[1][tid]
                                     + sacc[2][tid] + sacc[3][tid];
        // reduce ssum over 16 warps
        int lane = tid & 31, wid = tid >> 5;
        #pragma unroll
        for (int o = 16; o > 0; o >>= 1) ssum += __shfl_down_sync(0xffffffffu, ssum, o);
        if (lane == 0) sred[wid] = ssum;
        __syncthreads();
        if (wid == 0) {
            float v = (lane < 16) ? sred[lane] : 0.0f;
            #pragma unroll
            for (int o = 8; o > 0; o >>= 1) v += __shfl_down_sync(0xffffffffu, v, o);
            if (lane == 0) g_spart[blockIdx.x] = v;
        }
    }
    grid_sync();

    // ---- Phase 5: u[j] = sum_d y[d]*W1[d,j]  (blocks 0..15, 8 d's each);
    //      block 16 reduces sum_s ----
    if (blockIdx.x < 16) {
        int lane = tid & 31, wid = tid >> 5;
        int d0 = blockIdx.x * 8;
        if (wid < 8) {
            float v = 0.0f;
            for (int b = lane; b < NBLK; b += 32) v += g_ypart[b][d0 + wid];
            #pragma unroll
            for (int o = 16; o > 0; o >>= 1) v += __shfl_down_sync(0xffffffffu, v, o);
            if (lane == 0) svec[wid] = v;
        }
        __syncthreads();
        if (tid < DHID) {
            float p = 0.0f;
            #pragma unroll
            for (int d = 0; d < 8; d++)
                p += svec[d] * __ldg(&W1[(d0 + d) * DHID + tid]);
            atomicAdd(&g_u[tid], p);
        }
    } else if (blockIdx.x == 16) {
        if (tid < 32) {
            float v = 0.0f;
            for (int b = tid; b < NBLK; b += 32) v += g_spart[b];
            #pragma unroll
            for (int o = 16; o > 0; o >>= 1) v += __shfl_down_sync(0xffffffffu, v, o);
            if (tid == 0) g_sum_s = v;
        }
    }
    grid_sync();

    // ---- Phase 6: g[j] = sum_k (u[k] + sum_s*b1[k]) * W2[k,j]  (blocks 0..31) ----
    if (blockIdx.x < 32) {
        int k0 = blockIdx.x * 8;
        if (tid < 8) svec[tid] = g_u[k0 + tid] + g_sum_s * __ldg(&b1[k0 + tid]);
        __syncthreads();
        if (tid < DHID) {
            float p = 0.0f;
            #pragma unroll
            for (int k = 0; k < 8; k++)
                p += svec[k] * __ldg(&W2[(k0 + k) * DHID + tid]);
            atomicAdd(&g_g[tid], p);
        }
    }
    grid_sync();

    // ---- Phase 7: z[i] = sum_j (g[j]/n + b2[j]) * Wd1[j,i]  (blocks 0..31);
    //      block 32 re-zeroes g_u ----
    if (blockIdx.x < 32) {
        int j0 = blockIdx.x * 8;
        if (tid < 8) svec[tid] = g_g[j0 + tid] * invn + __ldg(&b2[j0 + tid]);
        __syncthreads();
        if (tid < DDNS) {
            float p = 0.0f;
            #pragma unroll
            for (int j = 0; j < 8; j++)
                p += svec[j] * __ldg(&Wd1[(j0 + j) * DDNS + tid]);
            atomicAdd(&g_z[tid], p);
        }
    } else if (blockIdx.x == 32) {
        if (tid < DHID) g_u[tid] = 0.0f;
    }
    grid_sync();

    // ---- Phase 8: logits + softmax (block 0); block 1 re-zeroes g_g ----
    if (blockIdx.x == 0) {
        if (tid < DDNS) {
            float zr = g_z[tid] + bd1[tid];
            g_z[tid] = 0.0f;                         // clean for next run
            float z  = zr > 0.0f ? zr : 0.0f;
            float p0 = z * __ldg(&Wd2[tid * 2 + 0]);
            float p1 = z * __ldg(&Wd2[tid * 2 + 1]);
            int lane = tid & 31, wid = tid >> 5;
            #pragma unroll
            for (int o = 16; o > 0; o >>= 1) {
                p0 += __shfl_down_sync(0xffffffffu, p0, o);
                p1 += __shfl_down_sync(0xffffffffu, p1, o);
            }
            if (lane == 0) { sp0[wid] = p0; sp1[wid] = p1; }
        }
        __syncthreads();
        if (tid == 0) {
            float l0 = bd2[0] + sp0[0] + sp0[1] + sp0[2] + sp0[3];
            float l1 = bd2[1] + sp1[0] + sp1[1] + sp1[2] + sp1[3];
            float m  = fmaxf(l0, l1);
            float e0 = __expf(l0 - m);
            float e1 = __expf(l1 - m);
            float inv = 1.0f / (e0 + e1);
            out[0] = e0 * inv;
            out[1] = e1 * inv;
        }
    } else if (blockIdx.x == 1) {
        if (tid < DHID) g_g[tid] = 0.0f;
    }
}

// ---------------------------------------------------------------------------
extern "C" void kernel_launch(void* const* d_in, const int* in_sizes, int n_in,
                              void* d_out, int out_size) {
    const float* X   = (const float*)d_in[0];
    const int*   ei  = (const int*)  d_in[1];
    const float* w   = (const float*)d_in[2];
    const float* W1  = (const float*)d_in[3];
    const float* b1  = (const float*)d_in[4];
    const float* W2  = (const float*)d_in[5];
    const float* b2  = (const float*)d_in[6];
    const float* Wd1 = (const float*)d_in[7];
    const float* bd1 = (const float*)d_in[8];
    const float* Wd2 = (const float*)d_in[9];
    const float* bd2 = (const float*)d_in[10];
    float* out = (float*)d_out;

    int n = in_sizes[0] / DIN;        // 20000
    int e = in_sizes[2];              // 640000
    const int* row = ei;
    const int* col = ei + e;
    int chunk = (n + NBLK - 1) / NBLK;

    k_main<<<NBLK, NTHR>>>(X, row, col, w, e, n, chunk,
                           W1, b1, W2, b2, Wd1, bd1, Wd2, bd2,
                           out, 1.0f / (float)n);
}